// round 1
// baseline (speedup 1.0000x reference)
#include <cuda_runtime.h>
#include <cuda_bf16.h>

// ---------------------------------------------------------------------------
// MS-SSIM loss, 3 scales, 11x11 separable Gaussian (sigma=1.5), zero padding.
// Fused per-scale kernel: load haloed tile -> fused 2x2 avg-pool for next
// scale -> separable blur of (x, y, x^2, y^2, x*y) -> per-pixel SSIM ->
// block reduction -> double atomic accumulate.
// ---------------------------------------------------------------------------

#define TILE   32
#define HALO   5
#define LDIM   42            // TILE + 2*HALO
#define SPITCH 44            // padded pitch for raw tiles
#define HPITCH 33            // padded pitch for blurred planes

// Normalized Gaussian taps (ws=11, sigma=1.5), computed in double, rounded.
__device__ __constant__ const float GW[11] = {
    0.00102838f, 0.00759875f, 0.03600077f, 0.10936069f, 0.21300553f,
    0.26601173f, 0.21300553f, 0.10936069f, 0.03600077f, 0.00759875f,
    0.00102838f
};
// constexpr copy so the unrolled loops fold taps into FFMA immediates
__device__ constexpr float GWC[11] = {
    0.00102838f, 0.00759875f, 0.03600077f, 0.10936069f, 0.21300553f,
    0.26601173f, 0.21300553f, 0.10936069f, 0.03600077f, 0.00759875f,
    0.00102838f
};

#define C1_ 0.0001f
#define C2_ 0.0009f

// Scratch for pooled pyramids (allocation-free: device globals)
__device__ float g_p1[64 * 256 * 256];
__device__ float g_t1[64 * 256 * 256];
__device__ float g_p2[64 * 128 * 128];
__device__ float g_t2[64 * 128 * 128];
__device__ double g_acc[3];

__global__ void zero_acc_kernel() {
    g_acc[0] = 0.0; g_acc[1] = 0.0; g_acc[2] = 0.0;
}

template <int H, int W, int SIDX, bool POOL>
__global__ __launch_bounds__(256)
void ssim_kernel(const float* __restrict__ pin, const float* __restrict__ tin)
{
    __shared__ float sx[LDIM][SPITCH];
    __shared__ float sy[LDIM][SPITCH];
    __shared__ float hpl[5][LDIM][HPITCH];
    __shared__ float red[8];

    const float* p;
    const float* t;
    float* pp;
    float* pt;
    if constexpr (SIDX == 0)      { p = pin;  t = tin;  pp = g_p1; pt = g_t1; }
    else if constexpr (SIDX == 1) { p = g_p1; t = g_t1; pp = g_p2; pt = g_t2; }
    else                          { p = g_p2; t = g_t2; pp = nullptr; pt = nullptr; }

    const int tx = threadIdx.x;          // 0..31
    const int ty = threadIdx.y;          // 0..7
    const int tid = ty * 32 + tx;
    const int x0 = blockIdx.x * TILE;
    const int y0 = blockIdx.y * TILE;
    const long imgBase = (long)blockIdx.z * H * W;

    // ---- Phase 1: load haloed raw tiles (zero padding outside image) ----
    #pragma unroll
    for (int i = tid; i < LDIM * LDIM; i += 256) {
        int r = i / LDIM, c = i - r * LDIM;
        int gy = y0 + r - HALO;
        int gx = x0 + c - HALO;
        float a = 0.0f, b = 0.0f;
        if (gy >= 0 && gy < H && gx >= 0 && gx < W) {
            long off = imgBase + (long)gy * W + gx;
            a = __ldg(p + off);
            b = __ldg(t + off);
        }
        sx[r][c] = a;
        sy[r][c] = b;
    }
    __syncthreads();

    // ---- Phase 2 (fused): 2x2 avg pool into next-scale scratch ----
    if constexpr (POOL) {
        const int pr = tid >> 4;         // 0..15
        const int pc = tid & 15;         // 0..15
        const int r = HALO + 2 * pr, c = HALO + 2 * pc;
        float a = 0.25f * (sx[r][c] + sx[r][c + 1] + sx[r + 1][c] + sx[r + 1][c + 1]);
        float b = 0.25f * (sy[r][c] + sy[r][c + 1] + sy[r + 1][c] + sy[r + 1][c + 1]);
        const int W2 = W / 2;
        long poff = (long)blockIdx.z * (H / 2) * W2
                  + (long)(y0 / 2 + pr) * W2 + (x0 / 2 + pc);
        pp[poff] = a;
        pt[poff] = b;
    }

    // ---- Phase 3: horizontal separable blur of 5 channels ----
    #pragma unroll
    for (int i = tid; i < LDIM * TILE; i += 256) {
        int r = i >> 5, c = i & 31;
        float hx = 0.f, hy = 0.f, hxx = 0.f, hyy = 0.f, hxy = 0.f;
        #pragma unroll
        for (int k = 0; k < 11; k++) {
            float a = sx[r][c + k];
            float b = sy[r][c + k];
            const float w = GWC[k];
            hx  = fmaf(a, w, hx);
            hy  = fmaf(b, w, hy);
            hxx = fmaf(a * a, w, hxx);
            hyy = fmaf(b * b, w, hyy);
            hxy = fmaf(a * b, w, hxy);
        }
        hpl[0][r][c] = hx;
        hpl[1][r][c] = hy;
        hpl[2][r][c] = hxx;
        hpl[3][r][c] = hyy;
        hpl[4][r][c] = hxy;
    }
    __syncthreads();

    // ---- Phase 4: vertical blur + SSIM. Each thread: 4 output rows, 1 col.
    float m0[4] = {0.f, 0.f, 0.f, 0.f};
    float m1[4] = {0.f, 0.f, 0.f, 0.f};
    float m2[4] = {0.f, 0.f, 0.f, 0.f};
    float m3[4] = {0.f, 0.f, 0.f, 0.f};
    float m4[4] = {0.f, 0.f, 0.f, 0.f};
    const int rbase = ty * 4;
    #pragma unroll
    for (int k = 0; k < 14; k++) {
        const int hr = rbase + k;
        float v0 = hpl[0][hr][tx];
        float v1 = hpl[1][hr][tx];
        float v2 = hpl[2][hr][tx];
        float v3 = hpl[3][hr][tx];
        float v4 = hpl[4][hr][tx];
        #pragma unroll
        for (int j = 0; j < 4; j++) {
            const int kk = k - j;
            if (kk >= 0 && kk < 11) {
                const float w = GWC[kk];
                m0[j] = fmaf(v0, w, m0[j]);
                m1[j] = fmaf(v1, w, m1[j]);
                m2[j] = fmaf(v2, w, m2[j]);
                m3[j] = fmaf(v3, w, m3[j]);
                m4[j] = fmaf(v4, w, m4[j]);
            }
        }
    }

    float acc = 0.0f;
    #pragma unroll
    for (int j = 0; j < 4; j++) {
        float mu1 = m0[j], mu2 = m1[j];
        float mu1sq = mu1 * mu1;
        float mu2sq = mu2 * mu2;
        float mu12  = mu1 * mu2;
        float s1  = m2[j] - mu1sq;
        float s2  = m3[j] - mu2sq;
        float s12 = m4[j] - mu12;
        float num = (2.0f * mu12 + C1_) * (2.0f * s12 + C2_);
        float den = (mu1sq + mu2sq + C1_) * (s1 + s2 + C2_);
        acc += __fdividef(num, den);
    }

    // ---- Phase 5: block reduction + global accumulate ----
    #pragma unroll
    for (int o = 16; o > 0; o >>= 1)
        acc += __shfl_down_sync(0xffffffffu, acc, o);
    if ((tid & 31) == 0) red[tid >> 5] = acc;
    __syncthreads();
    if (tid < 8) {
        float v = red[tid];
        #pragma unroll
        for (int o = 4; o > 0; o >>= 1)
            v += __shfl_down_sync(0xffu, v, o, 8);
        if (tid == 0) atomicAdd(&g_acc[SIDX], (double)v);
    }
}

__global__ void finalize_kernel(float* __restrict__ out) {
    const double n0 = 64.0 * 512.0 * 512.0;
    const double n1 = 64.0 * 256.0 * 256.0;
    const double n2 = 64.0 * 128.0 * 128.0;
    double ms = 0.5 * (g_acc[0] / n0) + 0.3 * (g_acc[1] / n1) + 0.2 * (g_acc[2] / n2);
    out[0] = (float)(1.0 - ms);
}

extern "C" void kernel_launch(void* const* d_in, const int* in_sizes, int n_in,
                              void* d_out, int out_size)
{
    const float* pred = (const float*)d_in[0];
    const float* targ = (const float*)d_in[1];
    float* out = (float*)d_out;

    dim3 blk(32, 8);
    zero_acc_kernel<<<1, 1>>>();
    ssim_kernel<512, 512, 0, true ><<<dim3(16, 16, 64), blk>>>(pred, targ);
    ssim_kernel<256, 256, 1, true ><<<dim3(8, 8, 64),  blk>>>(nullptr, nullptr);
    ssim_kernel<128, 128, 2, false><<<dim3(4, 4, 64),  blk>>>(nullptr, nullptr);
    finalize_kernel<<<1, 1>>>(out);
}

// round 2
// speedup vs baseline: 1.1248x; 1.1248x over previous
#include <cuda_runtime.h>
#include <cuda_bf16.h>

// ---------------------------------------------------------------------------
// MS-SSIM loss, 3 scales, 11x11 separable Gaussian (sigma=1.5), zero padding.
// R2: packed f32x2 math in both blur passes (channels paired: (x,y),(x2,y2)).
// ---------------------------------------------------------------------------

#define TILE    32
#define HALO    5
#define LDIM    42            // TILE + 2*HALO
#define SPITCH2 44            // raw tile pitch, in float2 units
#define HPITCH  33            // blurred plane pitch (elements)

__device__ constexpr float GWC[11] = {
    0.00102838f, 0.00759875f, 0.03600077f, 0.10936069f, 0.21300553f,
    0.26601173f, 0.21300553f, 0.10936069f, 0.03600077f, 0.00759875f,
    0.00102838f
};

#define C1_ 0.0001f
#define C2_ 0.0009f

// ---- packed f32x2 helpers (sm_103a) ----
typedef unsigned long long u64;

__device__ __forceinline__ u64 pack2(float a, float b) {
    u64 r; asm("mov.b64 %0, {%1, %2};" : "=l"(r) : "f"(a), "f"(b)); return r;
}
__device__ __forceinline__ void unpack2(u64 v, float& a, float& b) {
    asm("mov.b64 {%0, %1}, %2;" : "=f"(a), "=f"(b) : "l"(v));
}
__device__ __forceinline__ u64 fma2(u64 a, u64 b, u64 c) {
    u64 d; asm("fma.rn.f32x2 %0, %1, %2, %3;" : "=l"(d) : "l"(a), "l"(b), "l"(c)); return d;
}
__device__ __forceinline__ u64 mul2(u64 a, u64 b) {
    u64 d; asm("mul.rn.f32x2 %0, %1, %2;" : "=l"(d) : "l"(a), "l"(b)); return d;
}

// Scratch for pooled pyramids (allocation-free: device globals)
__device__ float2 g_s1[64 * 256 * 256];   // (pred, target) interleaved
__device__ float2 g_s2[64 * 128 * 128];
__device__ double g_acc[3];

__global__ void zero_acc_kernel() {
    g_acc[0] = 0.0; g_acc[1] = 0.0; g_acc[2] = 0.0;
}

template <int H, int W, int SIDX, bool POOL>
__global__ __launch_bounds__(256)
void ssim_kernel(const float* __restrict__ pin, const float* __restrict__ tin)
{
    __shared__ float2 sxy[LDIM][SPITCH2];        // (x, y) interleaved raw tile
    __shared__ float2 p01[LDIM][HPITCH];         // (hx, hy)
    __shared__ float2 p23[LDIM][HPITCH];         // (hxx, hyy)
    __shared__ float  p4 [LDIM][HPITCH];         // hxy
    __shared__ float  red[8];

    const int tx = threadIdx.x;          // 0..31
    const int ty = threadIdx.y;          // 0..7
    const int tid = ty * 32 + tx;
    const int x0 = blockIdx.x * TILE;
    const int y0 = blockIdx.y * TILE;

    // ---- Phase 1: load haloed raw tiles (zero padding outside image) ----
    if constexpr (SIDX == 0) {
        const long imgBase = (long)blockIdx.z * H * W;
        #pragma unroll
        for (int i = tid; i < LDIM * LDIM; i += 256) {
            int r = i / LDIM, c = i - r * LDIM;
            int gy = y0 + r - HALO;
            int gx = x0 + c - HALO;
            float a = 0.0f, b = 0.0f;
            if (gy >= 0 && gy < H && gx >= 0 && gx < W) {
                long off = imgBase + (long)gy * W + gx;
                a = __ldg(pin + off);
                b = __ldg(tin + off);
            }
            sxy[r][c] = make_float2(a, b);
        }
    } else {
        const float2* src = (SIDX == 1) ? g_s1 : g_s2;
        const long imgBase = (long)blockIdx.z * H * W;
        #pragma unroll
        for (int i = tid; i < LDIM * LDIM; i += 256) {
            int r = i / LDIM, c = i - r * LDIM;
            int gy = y0 + r - HALO;
            int gx = x0 + c - HALO;
            float2 v = make_float2(0.0f, 0.0f);
            if (gy >= 0 && gy < H && gx >= 0 && gx < W)
                v = __ldg(src + imgBase + (long)gy * W + gx);
            sxy[r][c] = v;
        }
    }
    __syncthreads();

    // ---- Phase 2 (fused): 2x2 avg pool into next-scale scratch ----
    if constexpr (POOL) {
        float2* dst = (SIDX == 0) ? g_s1 : g_s2;
        const int pr = tid >> 4;         // 0..15
        const int pc = tid & 15;         // 0..15
        const int r = HALO + 2 * pr, c = HALO + 2 * pc;
        float2 v00 = sxy[r][c],     v01 = sxy[r][c + 1];
        float2 v10 = sxy[r + 1][c], v11 = sxy[r + 1][c + 1];
        float a = 0.25f * (v00.x + v01.x + v10.x + v11.x);
        float b = 0.25f * (v00.y + v01.y + v10.y + v11.y);
        const int W2 = W / 2;
        long poff = (long)blockIdx.z * (H / 2) * W2
                  + (long)(y0 / 2 + pr) * W2 + (x0 / 2 + pc);
        dst[poff] = make_float2(a, b);
    }

    // packed tap weights (loop-invariant; compiler hoists / remats)
    u64 wp[11];
    #pragma unroll
    for (int k = 0; k < 11; k++) wp[k] = pack2(GWC[k], GWC[k]);

    // ---- Phase 3: horizontal separable blur (packed) ----
    #pragma unroll
    for (int i = tid; i < LDIM * TILE; i += 256) {
        int r = i >> 5, c = i & 31;
        const u64* row = (const u64*)&sxy[r][0];
        u64 hxy = 0, hsq = 0;
        float hab = 0.f;
        #pragma unroll
        for (int k = 0; k < 11; k++) {
            u64 p = row[c + k];
            hxy = fma2(p, wp[k], hxy);
            hsq = fma2(mul2(p, p), wp[k], hsq);
            float a, b; unpack2(p, a, b);
            hab = fmaf(a * b, GWC[k], hab);
        }
        *(u64*)&p01[r][c] = hxy;
        *(u64*)&p23[r][c] = hsq;
        p4[r][c] = hab;
    }
    __syncthreads();

    // ---- Phase 4: vertical blur + SSIM. Each thread: 4 output rows, 1 col.
    u64   mA[4] = {0, 0, 0, 0};   // (mu1, mu2)
    u64   mB[4] = {0, 0, 0, 0};   // (Exx, Eyy)
    float mC[4] = {0.f, 0.f, 0.f, 0.f};
    const int rbase = ty * 4;
    #pragma unroll
    for (int k = 0; k < 14; k++) {
        const int hr = rbase + k;
        u64 v01 = *(const u64*)&p01[hr][tx];
        u64 v23 = *(const u64*)&p23[hr][tx];
        float v4 = p4[hr][tx];
        #pragma unroll
        for (int j = 0; j < 4; j++) {
            const int kk = k - j;
            if (kk >= 0 && kk < 11) {
                mA[j] = fma2(v01, wp[kk], mA[j]);
                mB[j] = fma2(v23, wp[kk], mB[j]);
                mC[j] = fmaf(v4, GWC[kk], mC[j]);
            }
        }
    }

    float acc = 0.0f;
    #pragma unroll
    for (int j = 0; j < 4; j++) {
        float mu1, mu2, exx, eyy;
        unpack2(mA[j], mu1, mu2);
        unpack2(mB[j], exx, eyy);
        float mu1sq = mu1 * mu1;
        float mu2sq = mu2 * mu2;
        float mu12  = mu1 * mu2;
        float s1  = exx - mu1sq;
        float s2  = eyy - mu2sq;
        float s12 = mC[j] - mu12;
        float num = (2.0f * mu12 + C1_) * (2.0f * s12 + C2_);
        float den = (mu1sq + mu2sq + C1_) * (s1 + s2 + C2_);
        acc += __fdividef(num, den);
    }

    // ---- Phase 5: block reduction + global accumulate ----
    #pragma unroll
    for (int o = 16; o > 0; o >>= 1)
        acc += __shfl_down_sync(0xffffffffu, acc, o);
    if ((tid & 31) == 0) red[tid >> 5] = acc;
    __syncthreads();
    if (tid < 8) {
        float v = red[tid];
        #pragma unroll
        for (int o = 4; o > 0; o >>= 1)
            v += __shfl_down_sync(0xffu, v, o, 8);
        if (tid == 0) atomicAdd(&g_acc[SIDX], (double)v);
    }
}

__global__ void finalize_kernel(float* __restrict__ out) {
    const double n0 = 64.0 * 512.0 * 512.0;
    const double n1 = 64.0 * 256.0 * 256.0;
    const double n2 = 64.0 * 128.0 * 128.0;
    double ms = 0.5 * (g_acc[0] / n0) + 0.3 * (g_acc[1] / n1) + 0.2 * (g_acc[2] / n2);
    out[0] = (float)(1.0 - ms);
}

extern "C" void kernel_launch(void* const* d_in, const int* in_sizes, int n_in,
                              void* d_out, int out_size)
{
    const float* pred = (const float*)d_in[0];
    const float* targ = (const float*)d_in[1];
    float* out = (float*)d_out;

    dim3 blk(32, 8);
    zero_acc_kernel<<<1, 1>>>();
    ssim_kernel<512, 512, 0, true ><<<dim3(16, 16, 64), blk>>>(pred, targ);
    ssim_kernel<256, 256, 1, true ><<<dim3(8, 8, 64),  blk>>>(nullptr, nullptr);
    ssim_kernel<128, 128, 2, false><<<dim3(4, 4, 64),  blk>>>(nullptr, nullptr);
    finalize_kernel<<<1, 1>>>(out);
}

// round 3
// speedup vs baseline: 1.2669x; 1.1264x over previous
#include <cuda_runtime.h>
#include <cuda_bf16.h>

// ---------------------------------------------------------------------------
// MS-SSIM loss, 3 scales, 11x11 separable Gaussian (sigma=1.5), zero padding.
// R3: bf16x2 raw tiles + bf16x2 pooled scratch (smem 43K->34K, 6 blocks/SM),
//     no smem padding, paired horizontal outputs with ST.128.
// ---------------------------------------------------------------------------

#define TILE   32
#define HALO   5
#define LDIM   42            // TILE + 2*HALO
#define SPITCH 42            // raw tile pitch (bf16x2 units)
#define HPITCH 32            // blurred plane pitch

__device__ constexpr float GWC[11] = {
    0.00102838f, 0.00759875f, 0.03600077f, 0.10936069f, 0.21300553f,
    0.26601173f, 0.21300553f, 0.10936069f, 0.03600077f, 0.00759875f,
    0.00102838f
};

#define C1_ 0.0001f
#define C2_ 0.0009f

// ---- packed f32x2 helpers (sm_103a) ----
typedef unsigned long long u64;

__device__ __forceinline__ u64 pack2(float a, float b) {
    u64 r; asm("mov.b64 %0, {%1, %2};" : "=l"(r) : "f"(a), "f"(b)); return r;
}
__device__ __forceinline__ void unpack2(u64 v, float& a, float& b) {
    asm("mov.b64 {%0, %1}, %2;" : "=f"(a), "=f"(b) : "l"(v));
}
__device__ __forceinline__ u64 fma2(u64 a, u64 b, u64 c) {
    u64 d; asm("fma.rn.f32x2 %0, %1, %2, %3;" : "=l"(d) : "l"(a), "l"(b), "l"(c)); return d;
}
__device__ __forceinline__ u64 mul2(u64 a, u64 b) {
    u64 d; asm("mul.rn.f32x2 %0, %1, %2;" : "=l"(d) : "l"(a), "l"(b)); return d;
}

// Scratch for pooled pyramids (allocation-free: device globals), bf16x2
__device__ __nv_bfloat162 g_s1[64 * 256 * 256];   // (pred, target)
__device__ __nv_bfloat162 g_s2[64 * 128 * 128];
__device__ double g_acc[3];

__global__ void zero_acc_kernel() {
    g_acc[0] = 0.0; g_acc[1] = 0.0; g_acc[2] = 0.0;
}

template <int H, int W, int SIDX, bool POOL>
__global__ __launch_bounds__(256, 6)
void ssim_kernel(const float* __restrict__ pin, const float* __restrict__ tin)
{
    __shared__ __nv_bfloat162 sxy[LDIM][SPITCH];   // (x, y) raw tile, bf16x2
    __shared__ u64   p01[LDIM][HPITCH];            // (hx, hy)   fp32x2
    __shared__ u64   p23[LDIM][HPITCH];            // (hxx, hyy) fp32x2
    __shared__ float p4 [LDIM][HPITCH];            // hxy        fp32
    __shared__ float red[8];

    const int tx = threadIdx.x;          // 0..31
    const int ty = threadIdx.y;          // 0..7
    const int tid = ty * 32 + tx;
    const int x0 = blockIdx.x * TILE;
    const int y0 = blockIdx.y * TILE;

    // ---- Phase 1: load haloed raw tiles (zero padding outside image) ----
    if constexpr (SIDX == 0) {
        const long imgBase = (long)blockIdx.z * H * W;
        #pragma unroll
        for (int i = tid; i < LDIM * LDIM; i += 256) {
            int r = i / LDIM, c = i - r * LDIM;
            int gy = y0 + r - HALO;
            int gx = x0 + c - HALO;
            float a = 0.0f, b = 0.0f;
            if (gy >= 0 && gy < H && gx >= 0 && gx < W) {
                long off = imgBase + (long)gy * W + gx;
                a = __ldg(pin + off);
                b = __ldg(tin + off);
            }
            sxy[r][c] = __floats2bfloat162_rn(a, b);
        }
    } else {
        const __nv_bfloat162* src = (SIDX == 1) ? g_s1 : g_s2;
        const long imgBase = (long)blockIdx.z * H * W;
        #pragma unroll
        for (int i = tid; i < LDIM * LDIM; i += 256) {
            int r = i / LDIM, c = i - r * LDIM;
            int gy = y0 + r - HALO;
            int gx = x0 + c - HALO;
            __nv_bfloat162 v = __floats2bfloat162_rn(0.0f, 0.0f);
            if (gy >= 0 && gy < H && gx >= 0 && gx < W)
                v = __ldg(src + imgBase + (long)gy * W + gx);
            sxy[r][c] = v;
        }
    }
    __syncthreads();

    // ---- Phase 2 (fused): 2x2 avg pool into next-scale scratch ----
    if constexpr (POOL) {
        __nv_bfloat162* dst = (SIDX == 0) ? g_s1 : g_s2;
        const int pr = tid >> 4;         // 0..15
        const int pc = tid & 15;         // 0..15
        const int r = HALO + 2 * pr, c = HALO + 2 * pc;
        float2 v00 = __bfloat1622float2(sxy[r][c]);
        float2 v01 = __bfloat1622float2(sxy[r][c + 1]);
        float2 v10 = __bfloat1622float2(sxy[r + 1][c]);
        float2 v11 = __bfloat1622float2(sxy[r + 1][c + 1]);
        float a = 0.25f * (v00.x + v01.x + v10.x + v11.x);
        float b = 0.25f * (v00.y + v01.y + v10.y + v11.y);
        const int W2 = W / 2;
        long poff = (long)blockIdx.z * (H / 2) * W2
                  + (long)(y0 / 2 + pr) * W2 + (x0 / 2 + pc);
        dst[poff] = __floats2bfloat162_rn(a, b);
    }

    // packed tap weights (uniform-register candidates)
    u64 wp[11];
    #pragma unroll
    for (int k = 0; k < 11; k++) wp[k] = pack2(GWC[k], GWC[k]);

    // ---- Phase 3: horizontal blur, 2 adjacent outputs per iteration ----
    // 42 rows x 16 pair-columns = 672 work items
    #pragma unroll
    for (int it = 0; it < 3; it++) {
        const int i = tid + it * 256;
        if (i < 672) {
            const int r  = i >> 4;
            const int c0 = (i & 15) * 2;
            const __nv_bfloat162* row = &sxy[r][0];
            u64 hxy0 = 0, hsq0 = 0, hxy1 = 0, hsq1 = 0;
            float hab0 = 0.f, hab1 = 0.f;
            #pragma unroll
            for (int k = 0; k < 12; k++) {
                float2 f = __bfloat1622float2(row[c0 + k]);
                u64 p  = pack2(f.x, f.y);
                u64 sq = mul2(p, p);
                float ab = f.x * f.y;
                if (k < 11) {
                    hxy0 = fma2(p,  wp[k], hxy0);
                    hsq0 = fma2(sq, wp[k], hsq0);
                    hab0 = fmaf(ab, GWC[k], hab0);
                }
                if (k > 0) {
                    hxy1 = fma2(p,  wp[k - 1], hxy1);
                    hsq1 = fma2(sq, wp[k - 1], hsq1);
                    hab1 = fmaf(ab, GWC[k - 1], hab1);
                }
            }
            *(ulonglong2*)&p01[r][c0] = make_ulonglong2(hxy0, hxy1);
            *(ulonglong2*)&p23[r][c0] = make_ulonglong2(hsq0, hsq1);
            *(float2*)&p4[r][c0] = make_float2(hab0, hab1);
        }
    }
    __syncthreads();

    // ---- Phase 4: vertical blur + SSIM. Each thread: 4 output rows, 1 col.
    u64   mA[4] = {0, 0, 0, 0};   // (mu1, mu2)
    u64   mB[4] = {0, 0, 0, 0};   // (Exx, Eyy)
    float mC[4] = {0.f, 0.f, 0.f, 0.f};
    const int rbase = ty * 4;
    #pragma unroll
    for (int k = 0; k < 14; k++) {
        const int hr = rbase + k;
        u64 v01 = p01[hr][tx];
        u64 v23 = p23[hr][tx];
        float v4 = p4[hr][tx];
        #pragma unroll
        for (int j = 0; j < 4; j++) {
            const int kk = k - j;
            if (kk >= 0 && kk < 11) {
                mA[j] = fma2(v01, wp[kk], mA[j]);
                mB[j] = fma2(v23, wp[kk], mB[j]);
                mC[j] = fmaf(v4, GWC[kk], mC[j]);
            }
        }
    }

    float acc = 0.0f;
    #pragma unroll
    for (int j = 0; j < 4; j++) {
        float mu1, mu2, exx, eyy;
        unpack2(mA[j], mu1, mu2);
        unpack2(mB[j], exx, eyy);
        float mu1sq = mu1 * mu1;
        float mu2sq = mu2 * mu2;
        float mu12  = mu1 * mu2;
        float s1  = exx - mu1sq;
        float s2  = eyy - mu2sq;
        float s12 = mC[j] - mu12;
        float num = (2.0f * mu12 + C1_) * (2.0f * s12 + C2_);
        float den = (mu1sq + mu2sq + C1_) * (s1 + s2 + C2_);
        acc += __fdividef(num, den);
    }

    // ---- Phase 5: block reduction + global accumulate ----
    #pragma unroll
    for (int o = 16; o > 0; o >>= 1)
        acc += __shfl_down_sync(0xffffffffu, acc, o);
    if ((tid & 31) == 0) red[tid >> 5] = acc;
    __syncthreads();
    if (tid < 8) {
        float v = red[tid];
        #pragma unroll
        for (int o = 4; o > 0; o >>= 1)
            v += __shfl_down_sync(0xffu, v, o, 8);
        if (tid == 0) atomicAdd(&g_acc[SIDX], (double)v);
    }
}

__global__ void finalize_kernel(float* __restrict__ out) {
    const double n0 = 64.0 * 512.0 * 512.0;
    const double n1 = 64.0 * 256.0 * 256.0;
    const double n2 = 64.0 * 128.0 * 128.0;
    double ms = 0.5 * (g_acc[0] / n0) + 0.3 * (g_acc[1] / n1) + 0.2 * (g_acc[2] / n2);
    out[0] = (float)(1.0 - ms);
}

extern "C" void kernel_launch(void* const* d_in, const int* in_sizes, int n_in,
                              void* d_out, int out_size)
{
    const float* pred = (const float*)d_in[0];
    const float* targ = (const float*)d_in[1];
    float* out = (float*)d_out;

    dim3 blk(32, 8);
    zero_acc_kernel<<<1, 1>>>();
    ssim_kernel<512, 512, 0, true ><<<dim3(16, 16, 64), blk>>>(pred, targ);
    ssim_kernel<256, 256, 1, true ><<<dim3(8, 8, 64),  blk>>>(nullptr, nullptr);
    ssim_kernel<128, 128, 2, false><<<dim3(4, 4, 64),  blk>>>(nullptr, nullptr);
    finalize_kernel<<<1, 1>>>(out);
}

// round 4
// speedup vs baseline: 1.3287x; 1.0488x over previous
#include <cuda_runtime.h>
#include <cuda_bf16.h>

// ---------------------------------------------------------------------------
// MS-SSIM loss, 3 scales, 11x11 separable Gaussian (sigma=1.5), zero padding.
// R4: scale0 emits both pooled pyramids (2x2 and 4x4) -> scales 1+2 merged
//     into one launch; interleaved u64x2 plane for LDS.128 vertical loads;
//     shift-based bf16 decode; interior fast path; zero_acc folded into
//     finalize (read-then-reset).
// ---------------------------------------------------------------------------

#define TILE   32
#define HALO   5
#define LDIM   42            // TILE + 2*HALO
#define SPITCH 42            // raw tile pitch (bf16x2 units)

__device__ constexpr float GWC[11] = {
    0.00102838f, 0.00759875f, 0.03600077f, 0.10936069f, 0.21300553f,
    0.26601173f, 0.21300553f, 0.10936069f, 0.03600077f, 0.00759875f,
    0.00102838f
};

#define C1_ 0.0001f
#define C2_ 0.0009f

typedef unsigned long long u64;

__device__ __forceinline__ u64 pack2(float a, float b) {
    u64 r; asm("mov.b64 %0, {%1, %2};" : "=l"(r) : "f"(a), "f"(b)); return r;
}
__device__ __forceinline__ void unpack2(u64 v, float& a, float& b) {
    asm("mov.b64 {%0, %1}, %2;" : "=f"(a), "=f"(b) : "l"(v));
}
__device__ __forceinline__ u64 fma2(u64 a, u64 b, u64 c) {
    u64 d; asm("fma.rn.f32x2 %0, %1, %2, %3;" : "=l"(d) : "l"(a), "l"(b), "l"(c)); return d;
}
__device__ __forceinline__ u64 mul2(u64 a, u64 b) {
    u64 d; asm("mul.rn.f32x2 %0, %1, %2;" : "=l"(d) : "l"(a), "l"(b)); return d;
}
// bf16x2 -> two fp32 via pure bit ops (exact, alu lat 4 instead of cvt)
__device__ __forceinline__ void bf2dec(unsigned v, float& a, float& b) {
    a = __int_as_float((int)(v << 16));
    b = __int_as_float((int)(v & 0xffff0000u));
}

// Pooled pyramids (allocation-free device globals), bf16x2 (pred, target)
__device__ __nv_bfloat162 g_s1[64 * 256 * 256];
__device__ __nv_bfloat162 g_s2[64 * 128 * 128];
__device__ double g_acc[3];   // zero-initialized at load; reset by finalize

// ---------------------------------------------------------------------------
// Shared phases 3-5: horizontal blur, vertical blur + SSIM, reduction.
// ---------------------------------------------------------------------------
__device__ __forceinline__ void phases345(
    __nv_bfloat162 (&sxy)[LDIM][SPITCH],
    ulonglong2 (&pAB)[LDIM][TILE],
    float (&p4)[LDIM][TILE],
    float (&red)[8],
    int tx, int ty, int tid, int sidx)
{
    // packed tap weights
    u64 wp[11];
    #pragma unroll
    for (int k = 0; k < 11; k++) wp[k] = pack2(GWC[k], GWC[k]);

    // ---- horizontal blur, 2 adjacent outputs per item ----
    #pragma unroll
    for (int it = 0; it < 3; it++) {
        const int i = tid + it * 256;
        if (i < 672) {
            const int r  = i >> 4;
            const int c0 = (i & 15) * 2;
            const unsigned* row = (const unsigned*)&sxy[r][0];
            u64 hxy0 = 0, hsq0 = 0, hxy1 = 0, hsq1 = 0;
            float hab0 = 0.f, hab1 = 0.f;
            #pragma unroll
            for (int k = 0; k < 12; k++) {
                unsigned v = row[c0 + k];
                float a, b; bf2dec(v, a, b);
                u64 p  = pack2(a, b);
                u64 sq = mul2(p, p);
                float ab = a * b;
                if (k < 11) {
                    hxy0 = fma2(p,  wp[k], hxy0);
                    hsq0 = fma2(sq, wp[k], hsq0);
                    hab0 = fmaf(ab, GWC[k], hab0);
                }
                if (k > 0) {
                    hxy1 = fma2(p,  wp[k - 1], hxy1);
                    hsq1 = fma2(sq, wp[k - 1], hsq1);
                    hab1 = fmaf(ab, GWC[k - 1], hab1);
                }
            }
            pAB[r][c0]     = make_ulonglong2(hxy0, hsq0);
            pAB[r][c0 + 1] = make_ulonglong2(hxy1, hsq1);
            *(float2*)&p4[r][c0] = make_float2(hab0, hab1);
        }
    }
    __syncthreads();

    // ---- vertical blur + SSIM: 4 output rows per thread, 1 col ----
    u64   mA[4] = {0, 0, 0, 0};
    u64   mB[4] = {0, 0, 0, 0};
    float mC[4] = {0.f, 0.f, 0.f, 0.f};
    const int rbase = ty * 4;
    #pragma unroll
    for (int k = 0; k < 14; k++) {
        const int hr = rbase + k;
        ulonglong2 vab = pAB[hr][tx];          // LDS.128
        float v4 = p4[hr][tx];
        #pragma unroll
        for (int j = 0; j < 4; j++) {
            const int kk = k - j;
            if (kk >= 0 && kk < 11) {
                mA[j] = fma2(vab.x, wp[kk], mA[j]);
                mB[j] = fma2(vab.y, wp[kk], mB[j]);
                mC[j] = fmaf(v4, GWC[kk], mC[j]);
            }
        }
    }

    float acc = 0.0f;
    #pragma unroll
    for (int j = 0; j < 4; j++) {
        float mu1, mu2, exx, eyy;
        unpack2(mA[j], mu1, mu2);
        unpack2(mB[j], exx, eyy);
        float mu1sq = mu1 * mu1;
        float mu2sq = mu2 * mu2;
        float mu12  = mu1 * mu2;
        float s1  = exx - mu1sq;
        float s2  = eyy - mu2sq;
        float s12 = mC[j] - mu12;
        float num = (2.0f * mu12 + C1_) * (2.0f * s12 + C2_);
        float den = (mu1sq + mu2sq + C1_) * (s1 + s2 + C2_);
        acc += __fdividef(num, den);
    }

    #pragma unroll
    for (int o = 16; o > 0; o >>= 1)
        acc += __shfl_down_sync(0xffffffffu, acc, o);
    if ((tid & 31) == 0) red[tid >> 5] = acc;
    __syncthreads();
    if (tid < 8) {
        float v = red[tid];
        #pragma unroll
        for (int o = 4; o > 0; o >>= 1)
            v += __shfl_down_sync(0xffu, v, o, 8);
        if (tid == 0) atomicAdd(&g_acc[sidx], (double)v);
    }
}

// ---------------------------------------------------------------------------
// Scale 0: fp32 global inputs, writes BOTH pooled pyramids, then SSIM.
// ---------------------------------------------------------------------------
__global__ __launch_bounds__(256, 6)
void ssim_scale0_kernel(const float* __restrict__ pin, const float* __restrict__ tin)
{
    __shared__ __nv_bfloat162 sxy[LDIM][SPITCH];
    __shared__ ulonglong2 pAB[LDIM][TILE];
    __shared__ float p4[LDIM][TILE];
    __shared__ float red[8];

    const int tx = threadIdx.x, ty = threadIdx.y;
    const int tid = ty * 32 + tx;
    const int x0 = blockIdx.x * TILE;
    const int y0 = blockIdx.y * TILE;
    const int H = 512, W = 512;
    const long imgBase = (long)blockIdx.z * H * W;

    const bool interior = (x0 >= HALO) && (y0 >= HALO) &&
                          (x0 + TILE + HALO <= W) && (y0 + TILE + HALO <= H);
    if (interior) {
        #pragma unroll
        for (int i = tid; i < LDIM * LDIM; i += 256) {
            int r = i / LDIM, c = i - r * LDIM;
            long off = imgBase + (long)(y0 + r - HALO) * W + (x0 + c - HALO);
            float a = __ldg(pin + off);
            float b = __ldg(tin + off);
            sxy[r][c] = __floats2bfloat162_rn(a, b);
        }
    } else {
        #pragma unroll
        for (int i = tid; i < LDIM * LDIM; i += 256) {
            int r = i / LDIM, c = i - r * LDIM;
            int gy = y0 + r - HALO;
            int gx = x0 + c - HALO;
            float a = 0.0f, b = 0.0f;
            if (gy >= 0 && gy < H && gx >= 0 && gx < W) {
                long off = imgBase + (long)gy * W + gx;
                a = __ldg(pin + off);
                b = __ldg(tin + off);
            }
            sxy[r][c] = __floats2bfloat162_rn(a, b);
        }
    }
    __syncthreads();

    // 2x2 pool -> g_s1 (one output px per thread: 16x16)
    {
        const int pr = tid >> 4;
        const int pc = tid & 15;
        const int r = HALO + 2 * pr, c = HALO + 2 * pc;
        float a0, b0, a1, b1, a2, b2, a3, b3;
        bf2dec(*(const unsigned*)&sxy[r][c],         a0, b0);
        bf2dec(*(const unsigned*)&sxy[r][c + 1],     a1, b1);
        bf2dec(*(const unsigned*)&sxy[r + 1][c],     a2, b2);
        bf2dec(*(const unsigned*)&sxy[r + 1][c + 1], a3, b3);
        float a = 0.25f * (a0 + a1 + a2 + a3);
        float b = 0.25f * (b0 + b1 + b2 + b3);
        long poff = (long)blockIdx.z * 256 * 256
                  + (long)(y0 / 2 + pr) * 256 + (x0 / 2 + pc);
        g_s1[poff] = __floats2bfloat162_rn(a, b);
    }
    // 4x4 pool -> g_s2 (8x8 outputs per tile, threads 0..63)
    if (tid < 64) {
        const int pr = tid >> 3;
        const int pc = tid & 7;
        const int r = HALO + 4 * pr, c = HALO + 4 * pc;
        float sa = 0.f, sb = 0.f;
        #pragma unroll
        for (int dr = 0; dr < 4; dr++)
            #pragma unroll
            for (int dc = 0; dc < 4; dc++) {
                float a, b;
                bf2dec(*(const unsigned*)&sxy[r + dr][c + dc], a, b);
                sa += a; sb += b;
            }
        long poff = (long)blockIdx.z * 128 * 128
                  + (long)(y0 / 4 + pr) * 128 + (x0 / 4 + pc);
        g_s2[poff] = __floats2bfloat162_rn(sa * 0.0625f, sb * 0.0625f);
    }

    phases345(sxy, pAB, p4, red, tx, ty, tid, 0);
}

// ---------------------------------------------------------------------------
// Scales 1+2 merged: z < 64 -> scale1 (256x256), z >= 64 -> scale2 (128x128).
// ---------------------------------------------------------------------------
__global__ __launch_bounds__(256, 6)
void ssim_small_kernel()
{
    __shared__ __nv_bfloat162 sxy[LDIM][SPITCH];
    __shared__ ulonglong2 pAB[LDIM][TILE];
    __shared__ float p4[LDIM][TILE];
    __shared__ float red[8];

    const int tx = threadIdx.x, ty = threadIdx.y;
    const int tid = ty * 32 + tx;
    const int z = blockIdx.z;

    const __nv_bfloat162* src;
    int x0, y0, img, H, sidx;
    if (z < 64) {
        src = g_s1; H = 256; sidx = 1;
        x0 = blockIdx.x * TILE; y0 = blockIdx.y * TILE; img = z;
    } else {
        src = g_s2; H = 128; sidx = 2;
        const int z2 = z - 64;
        img = z2 * 4 + ((blockIdx.y >> 2) << 1) + (blockIdx.x >> 2);
        x0 = (blockIdx.x & 3) * TILE;
        y0 = (blockIdx.y & 3) * TILE;
    }
    const int W = H;
    const long imgBase = (long)img * H * W;

    const bool interior = (x0 >= HALO) && (y0 >= HALO) &&
                          (x0 + TILE + HALO <= W) && (y0 + TILE + HALO <= H);
    if (interior) {
        #pragma unroll
        for (int i = tid; i < LDIM * LDIM; i += 256) {
            int r = i / LDIM, c = i - r * LDIM;
            sxy[r][c] = __ldg(src + imgBase + (long)(y0 + r - HALO) * W + (x0 + c - HALO));
        }
    } else {
        #pragma unroll
        for (int i = tid; i < LDIM * LDIM; i += 256) {
            int r = i / LDIM, c = i - r * LDIM;
            int gy = y0 + r - HALO;
            int gx = x0 + c - HALO;
            __nv_bfloat162 v; *(unsigned*)&v = 0u;
            if (gy >= 0 && gy < H && gx >= 0 && gx < W)
                v = __ldg(src + imgBase + (long)gy * W + gx);
            sxy[r][c] = v;
        }
    }
    __syncthreads();

    phases345(sxy, pAB, p4, red, tx, ty, tid, sidx);
}

__global__ void finalize_kernel(float* __restrict__ out) {
    const double n0 = 64.0 * 512.0 * 512.0;
    const double n1 = 64.0 * 256.0 * 256.0;
    const double n2 = 64.0 * 128.0 * 128.0;
    double ms = 0.5 * (g_acc[0] / n0) + 0.3 * (g_acc[1] / n1) + 0.2 * (g_acc[2] / n2);
    out[0] = (float)(1.0 - ms);
    // reset for the next graph replay (globals start zeroed at module load)
    g_acc[0] = 0.0; g_acc[1] = 0.0; g_acc[2] = 0.0;
}

extern "C" void kernel_launch(void* const* d_in, const int* in_sizes, int n_in,
                              void* d_out, int out_size)
{
    const float* pred = (const float*)d_in[0];
    const float* targ = (const float*)d_in[1];
    float* out = (float*)d_out;

    dim3 blk(32, 8);
    ssim_scale0_kernel<<<dim3(16, 16, 64), blk>>>(pred, targ);
    ssim_small_kernel<<<dim3(8, 8, 80), blk>>>();
    finalize_kernel<<<1, 1>>>(out);
}